// round 1
// baseline (speedup 1.0000x reference)
#include <cuda_runtime.h>
#include <cuda_bf16.h>

// Problem constants (match reference setup_inputs)
#define B   4096
#define S   200
#define E   300
#define TAGS 2

// Scratch (allocation-free rule: __device__ globals)
__device__ float g_pooled[B * E];
__device__ float g_h1[B * E];
__device__ float g_h2[B * E];

// ---------------------------------------------------------------------------
// Kernel 1: gather + mean pool.  One CTA per batch row.
// pooled[b, d] = (1/S) * sum_t emb[x[b,t], d]
// Threads d = 0..299 each own one embedding dim -> consecutive threads read
// consecutive floats of each embedding row (coalesced 1200B row reads).
// ---------------------------------------------------------------------------
__global__ __launch_bounds__(320) void pool_kernel(
    const int* __restrict__ x,
    const float* __restrict__ emb,
    float* __restrict__ pooled)
{
    __shared__ int ids[S];
    const int b = blockIdx.x;

    for (int t = threadIdx.x; t < S; t += blockDim.x)
        ids[t] = x[b * S + t];
    __syncthreads();

    const int d = threadIdx.x;
    if (d >= E) return;

    float acc = 0.0f;
#pragma unroll 8
    for (int t = 0; t < S; ++t) {
        // id*E fits easily in int32 (500000*300 = 1.5e8)
        acc += __ldg(&emb[ids[t] * E + d]);
    }
    pooled[b * E + d] = acc * (1.0f / (float)S);
}

// ---------------------------------------------------------------------------
// Kernel 2/3: C[m,n] = relu( sum_k A[m,k] * W[n,k] )
// A: [M, K] row-major, W: [N, K] row-major (nn.Linear weight), C: [M, N].
// 64x64 block tile, BK=16, 256 threads, 4x4 microtile per thread.
// ---------------------------------------------------------------------------
template <bool RELU>
__global__ __launch_bounds__(256) void gemm_wt(
    const float* __restrict__ A,
    const float* __restrict__ W,
    float* __restrict__ C,
    int M, int N, int K)
{
    const int BM = 64, BN = 64, BK = 16;
    __shared__ float As[BK][BM + 1];   // [k][m], padded
    __shared__ float Ws[BK][BN + 1];   // [k][n], padded

    const int m0 = blockIdx.x * BM;
    const int n0 = blockIdx.y * BN;

    const int tid = threadIdx.x;
    const int tx = tid % 16;   // n direction
    const int ty = tid / 16;   // m direction

    // loader mapping: each thread loads 4 consecutive k for one row
    const int lrow = tid / 4;          // 0..63
    const int lk0  = (tid % 4) * 4;    // 0,4,8,12

    float c[4][4];
#pragma unroll
    for (int i = 0; i < 4; ++i)
#pragma unroll
        for (int j = 0; j < 4; ++j) c[i][j] = 0.0f;

    for (int k0 = 0; k0 < K; k0 += BK) {
        // Load A tile: rows m0+lrow, cols k0+lk0..+3 -> As[k][m]
        {
            int m = m0 + lrow;
#pragma unroll
            for (int i = 0; i < 4; ++i) {
                int k = k0 + lk0 + i;
                float v = 0.0f;
                if (m < M && k < K) v = A[m * K + k];
                As[lk0 + i][lrow] = v;
            }
        }
        // Load W tile: rows n0+lrow, cols k0+lk0..+3 -> Ws[k][n]
        {
            int n = n0 + lrow;
#pragma unroll
            for (int i = 0; i < 4; ++i) {
                int k = k0 + lk0 + i;
                float v = 0.0f;
                if (n < N && k < K) v = W[n * K + k];
                Ws[lk0 + i][lrow] = v;
            }
        }
        __syncthreads();

#pragma unroll
        for (int kk = 0; kk < BK; ++kk) {
            float a[4], w[4];
#pragma unroll
            for (int i = 0; i < 4; ++i) a[i] = As[kk][ty * 4 + i];
#pragma unroll
            for (int j = 0; j < 4; ++j) w[j] = Ws[kk][tx * 4 + j];
#pragma unroll
            for (int i = 0; i < 4; ++i)
#pragma unroll
                for (int j = 0; j < 4; ++j)
                    c[i][j] = fmaf(a[i], w[j], c[i][j]);
        }
        __syncthreads();
    }

#pragma unroll
    for (int i = 0; i < 4; ++i) {
        int m = m0 + ty * 4 + i;
        if (m >= M) continue;
#pragma unroll
        for (int j = 0; j < 4; ++j) {
            int n = n0 + tx * 4 + j;
            if (n >= N) continue;
            float v = c[i][j];
            if (RELU) v = fmaxf(v, 0.0f);
            C[m * N + n] = v;
        }
    }
}

// ---------------------------------------------------------------------------
// Kernel 4: out[b, t] = sum_k h2[b,k] * w3[t,k],  t in {0,1}
// One warp per batch row; w3 (600 floats) staged in smem.
// ---------------------------------------------------------------------------
__global__ __launch_bounds__(256) void final_kernel(
    const float* __restrict__ H,
    const float* __restrict__ W3,
    float* __restrict__ out)
{
    __shared__ float w[TAGS * E];
    for (int i = threadIdx.x; i < TAGS * E; i += blockDim.x)
        w[i] = W3[i];
    __syncthreads();

    const int warp = threadIdx.x >> 5;
    const int lane = threadIdx.x & 31;
    const int b = blockIdx.x * 8 + warp;
    if (b >= B) return;

    float s0 = 0.0f, s1 = 0.0f;
    for (int k = lane; k < E; k += 32) {
        float h = H[b * E + k];
        s0 = fmaf(h, w[k], s0);
        s1 = fmaf(h, w[E + k], s1);
    }
#pragma unroll
    for (int o = 16; o > 0; o >>= 1) {
        s0 += __shfl_down_sync(0xFFFFFFFFu, s0, o);
        s1 += __shfl_down_sync(0xFFFFFFFFu, s1, o);
    }
    if (lane == 0) {
        out[b * TAGS + 0] = s0;
        out[b * TAGS + 1] = s1;
    }
}

// ---------------------------------------------------------------------------
// Launch
// inputs (metadata order): x [B*S] int32, emb [VOCAB*E] f32,
//                          w1 [E*E] f32, w2 [E*E] f32, w3 [TAGS*E] f32
// output: [B*TAGS] f32
// ---------------------------------------------------------------------------
extern "C" void kernel_launch(void* const* d_in, const int* in_sizes, int n_in,
                              void* d_out, int out_size)
{
    const int*   x   = (const int*)d_in[0];
    const float* emb = (const float*)d_in[1];
    const float* w1  = (const float*)d_in[2];
    const float* w2  = (const float*)d_in[3];
    const float* w3  = (const float*)d_in[4];
    float* out = (float*)d_out;

    float* pooled; cudaGetSymbolAddress((void**)&pooled, g_pooled);
    float* h1;     cudaGetSymbolAddress((void**)&h1, g_h1);
    float* h2;     cudaGetSymbolAddress((void**)&h2, g_h2);

    // 1) gather + mean pool
    pool_kernel<<<B, 320>>>(x, emb, pooled);

    // 2) h1 = relu(pooled @ w1^T)
    {
        dim3 grid(B / 64, (E + 63) / 64);
        gemm_wt<true><<<grid, 256>>>(pooled, w1, h1, B, E, E);
    }
    // 3) h2 = relu(h1 @ w2^T)
    {
        dim3 grid(B / 64, (E + 63) / 64);
        gemm_wt<true><<<grid, 256>>>(h1, w2, h2, B, E, E);
    }
    // 4) out = h2 @ w3^T
    final_kernel<<<B / 8, 256>>>(h2, w3, out);
}

// round 2
// speedup vs baseline: 1.1485x; 1.1485x over previous
#include <cuda_runtime.h>
#include <cuda_bf16.h>

// Problem constants (match reference setup_inputs)
#define B    4096
#define S    200
#define E    300
#define TAGS 2
#define EV4  (E / 4)   // 75 float4 per embedding row

// Scratch (allocation-free rule: __device__ globals)
__device__ float g_pooled[B * E];
__device__ float g_h1[B * E];

// ---------------------------------------------------------------------------
// Kernel 1: gather + mean pool.  One CTA per batch row, 300 threads.
// 4 groups of 75 threads; group g handles tokens t = g, g+4, ... (50 each).
// Each thread accumulates one float4 (4 embedding dims) -> 4x fewer LDGs,
// 4x more independent load streams than the scalar version.
// ---------------------------------------------------------------------------
__global__ __launch_bounds__(300) void pool_kernel(
    const int* __restrict__ x,
    const float* __restrict__ emb,
    float* __restrict__ pooled)
{
    __shared__ int ids[S];
    __shared__ float4 red[3][EV4];

    const int b = blockIdx.x;
    for (int t = threadIdx.x; t < S; t += 300)
        ids[t] = x[b * S + t];
    __syncthreads();

    const int g = threadIdx.x / EV4;   // 0..3  token group
    const int l = threadIdx.x % EV4;   // 0..74 float4 slot within row

    const float4* __restrict__ embv = (const float4*)emb;

    float4 acc = make_float4(0.f, 0.f, 0.f, 0.f);
#pragma unroll 5
    for (int i = 0; i < S / 4; ++i) {
        // id*75 <= 37.5M : fits int32
        const int id = ids[i * 4 + g];
        float4 v = __ldg(&embv[id * EV4 + l]);
        acc.x += v.x; acc.y += v.y; acc.z += v.z; acc.w += v.w;
    }

    if (g > 0) red[g - 1][l] = acc;
    __syncthreads();

    if (g == 0) {
#pragma unroll
        for (int j = 0; j < 3; ++j) {
            float4 v = red[j][l];
            acc.x += v.x; acc.y += v.y; acc.z += v.z; acc.w += v.w;
        }
        const float inv = 1.0f / (float)S;
        float4 r = make_float4(acc.x * inv, acc.y * inv, acc.z * inv, acc.w * inv);
        ((float4*)pooled)[b * EV4 + l] = r;
    }
}

// ---------------------------------------------------------------------------
// Zero the output (d_out is poisoned; fused epilogue accumulates atomically).
// ---------------------------------------------------------------------------
__global__ void zero_kernel(float* __restrict__ out, int n)
{
    int i = blockIdx.x * blockDim.x + threadIdx.x;
    if (i < n) out[i] = 0.0f;
}

// ---------------------------------------------------------------------------
// GEMM: C[m,n] = relu( sum_k A[m,k] * W[n,k] )
// A: [M,K] row-major, W: [N,K] row-major (nn.Linear weight).
// 64x64 tile, BK=16, 256 threads, 4x4 microtile. float4 global loads.
//
// EPI == 0 : write relu(C) to Cout.
// EPI == 1 : fused head. Instead of storing C, compute
//            out[m,t] += sum_n relu(C[m,n]) * w3[t,n]
//            via half-warp shuffle reduce + atomicAdd (out pre-zeroed).
// ---------------------------------------------------------------------------
template <int EPI>
__global__ __launch_bounds__(256) void gemm_wt(
    const float* __restrict__ A,
    const float* __restrict__ W,
    float* __restrict__ Cout,          // EPI==0: [M,N] output; EPI==1: unused
    const float* __restrict__ W3,      // EPI==1: [TAGS,E]
    float* __restrict__ out,           // EPI==1: [M,TAGS]
    int M, int N, int K)
{
    const int BM = 64, BN = 64, BK = 16;
    __shared__ float As[BK][BM + 1];
    __shared__ float Ws[BK][BN + 1];
    __shared__ float w3s[TAGS * E];

    const int tid = threadIdx.x;

    if (EPI == 1) {
        for (int i = tid; i < TAGS * E; i += 256)
            w3s[i] = W3[i];
    }

    const int m0 = blockIdx.x * BM;
    const int n0 = blockIdx.y * BN;

    const int tx = tid % 16;   // n direction
    const int ty = tid / 16;   // m direction

    const int lrow = tid / 4;          // 0..63
    const int lk0  = (tid % 4) * 4;    // 0,4,8,12

    float c[4][4];
#pragma unroll
    for (int i = 0; i < 4; ++i)
#pragma unroll
        for (int j = 0; j < 4; ++j) c[i][j] = 0.0f;

    for (int k0 = 0; k0 < K; k0 += BK) {
        const int k = k0 + lk0;
        // A tile (m0+lrow always < M since M % 64 == 0)
        {
            const int m = m0 + lrow;
            float4 av = make_float4(0.f, 0.f, 0.f, 0.f);
            if (k + 3 < K) {
                av = *(const float4*)&A[m * K + k];
            } else {
                if (k + 0 < K) av.x = A[m * K + k + 0];
                if (k + 1 < K) av.y = A[m * K + k + 1];
                if (k + 2 < K) av.z = A[m * K + k + 2];
                if (k + 3 < K) av.w = A[m * K + k + 3];
            }
            As[lk0 + 0][lrow] = av.x;
            As[lk0 + 1][lrow] = av.y;
            As[lk0 + 2][lrow] = av.z;
            As[lk0 + 3][lrow] = av.w;
        }
        // W tile (n can exceed N=300)
        {
            const int n = n0 + lrow;
            float4 wv = make_float4(0.f, 0.f, 0.f, 0.f);
            if (n < N) {
                if (k + 3 < K) {
                    wv = *(const float4*)&W[n * K + k];
                } else {
                    if (k + 0 < K) wv.x = W[n * K + k + 0];
                    if (k + 1 < K) wv.y = W[n * K + k + 1];
                    if (k + 2 < K) wv.z = W[n * K + k + 2];
                    if (k + 3 < K) wv.w = W[n * K + k + 3];
                }
            }
            Ws[lk0 + 0][lrow] = wv.x;
            Ws[lk0 + 1][lrow] = wv.y;
            Ws[lk0 + 2][lrow] = wv.z;
            Ws[lk0 + 3][lrow] = wv.w;
        }
        __syncthreads();

#pragma unroll
        for (int kk = 0; kk < BK; ++kk) {
            float a[4], w[4];
#pragma unroll
            for (int i = 0; i < 4; ++i) a[i] = As[kk][ty * 4 + i];
#pragma unroll
            for (int j = 0; j < 4; ++j) w[j] = Ws[kk][tx * 4 + j];
#pragma unroll
            for (int i = 0; i < 4; ++i)
#pragma unroll
                for (int j = 0; j < 4; ++j)
                    c[i][j] = fmaf(a[i], w[j], c[i][j]);
        }
        __syncthreads();
    }

    if (EPI == 0) {
#pragma unroll
        for (int i = 0; i < 4; ++i) {
            const int m = m0 + ty * 4 + i;
#pragma unroll
            for (int j = 0; j < 4; ++j) {
                const int n = n0 + tx * 4 + j;
                if (n < N) Cout[m * N + n] = fmaxf(c[i][j], 0.0f);
            }
        }
    } else {
        // Fused head: s[i][t] = sum over this thread's 4 n-values
        float s[4][2];
#pragma unroll
        for (int i = 0; i < 4; ++i) { s[i][0] = 0.f; s[i][1] = 0.f; }
#pragma unroll
        for (int j = 0; j < 4; ++j) {
            const int n = n0 + tx * 4 + j;
            if (n < N) {
                const float w0 = w3s[n];
                const float w1 = w3s[E + n];
#pragma unroll
                for (int i = 0; i < 4; ++i) {
                    const float v = fmaxf(c[i][j], 0.0f);
                    s[i][0] = fmaf(v, w0, s[i][0]);
                    s[i][1] = fmaf(v, w1, s[i][1]);
                }
            }
        }
        // Reduce across the 16 tx lanes (each half-warp has constant ty)
#pragma unroll
        for (int off = 8; off > 0; off >>= 1) {
#pragma unroll
            for (int i = 0; i < 4; ++i) {
                s[i][0] += __shfl_xor_sync(0xFFFFFFFFu, s[i][0], off);
                s[i][1] += __shfl_xor_sync(0xFFFFFFFFu, s[i][1], off);
            }
        }
        if (tx == 0) {
#pragma unroll
            for (int i = 0; i < 4; ++i) {
                const int m = m0 + ty * 4 + i;
                atomicAdd(&out[m * TAGS + 0], s[i][0]);
                atomicAdd(&out[m * TAGS + 1], s[i][1]);
            }
        }
    }
}

// ---------------------------------------------------------------------------
// Launch
// inputs (metadata order): x [B*S] int32, emb [VOCAB*E] f32,
//                          w1 [E*E] f32, w2 [E*E] f32, w3 [TAGS*E] f32
// output: [B*TAGS] f32
// ---------------------------------------------------------------------------
extern "C" void kernel_launch(void* const* d_in, const int* in_sizes, int n_in,
                              void* d_out, int out_size)
{
    const int*   x   = (const int*)d_in[0];
    const float* emb = (const float*)d_in[1];
    const float* w1  = (const float*)d_in[2];
    const float* w2  = (const float*)d_in[3];
    const float* w3  = (const float*)d_in[4];
    float* out = (float*)d_out;

    float* pooled; cudaGetSymbolAddress((void**)&pooled, g_pooled);
    float* h1;     cudaGetSymbolAddress((void**)&h1, g_h1);

    // 1) gather + mean pool
    pool_kernel<<<B, 300>>>(x, emb, pooled);

    // 2) zero the fused-head accumulator (d_out is poisoned)
    zero_kernel<<<(B * TAGS + 255) / 256, 256>>>(out, B * TAGS);

    // 3) h1 = relu(pooled @ w1^T)
    {
        dim3 grid(B / 64, (E + 63) / 64);
        gemm_wt<0><<<grid, 256>>>(pooled, w1, h1, nullptr, nullptr, B, E, E);
    }
    // 4) out = relu(h1 @ w2^T) @ w3^T   (fused epilogue, atomic accumulate)
    {
        dim3 grid(B / 64, (E + 63) / 64);
        gemm_wt<1><<<grid, 256>>>(h1, w2, nullptr, w3, out, B, E, E);
    }
}